// round 1
// baseline (speedup 1.0000x reference)
#include <cuda_runtime.h>
#include <math.h>

#define TOKENS 8192
#define DM 1024
#define DF 2048
#define NE 8

// Scratch (device globals: allocation-free, graph-safe)
__device__ int   g_cnt[2];
__device__ int   g_idx[2][TOKENS];
__device__ float g_scale[2][TOKENS];
__device__ float g_h[2][(size_t)TOKENS * DF];   // gelu activations, compacted rows

__global__ void reset_kernel() {
    if (threadIdx.x < 2) g_cnt[threadIdx.x] = 0;
}

// One warp per token: logits -> softmax -> top-2 -> compact active tokens.
__global__ __launch_bounds__(256) void gate_kernel(const float* __restrict__ x,
                                                   const float* __restrict__ gw,
                                                   const float* __restrict__ gb) {
    __shared__ float sgw[DM * NE];
    for (int i = threadIdx.x; i < DM * NE; i += 256) sgw[i] = gw[i];
    __syncthreads();

    const int t    = (int)((blockIdx.x * 256u + threadIdx.x) >> 5);
    const int lane = threadIdx.x & 31;
    if (t >= TOKENS) return;

    const float* xr = x + (size_t)t * DM;
    float acc[NE];
#pragma unroll
    for (int e = 0; e < NE; e++) acc[e] = 0.f;

    for (int d = lane; d < DM; d += 32) {
        float xv = xr[d];
        const float4* wp = (const float4*)(sgw + d * NE);
        float4 w0 = wp[0];
        float4 w1 = wp[1];
        acc[0] += xv * w0.x; acc[1] += xv * w0.y;
        acc[2] += xv * w0.z; acc[3] += xv * w0.w;
        acc[4] += xv * w1.x; acc[5] += xv * w1.y;
        acc[6] += xv * w1.z; acc[7] += xv * w1.w;
    }
#pragma unroll
    for (int e = 0; e < NE; e++) {
#pragma unroll
        for (int o = 16; o > 0; o >>= 1)
            acc[e] += __shfl_xor_sync(0xffffffffu, acc[e], o);
    }

    if (lane == 0) {
        float p[NE];
        float mx = -1e30f;
#pragma unroll
        for (int e = 0; e < NE; e++) { p[e] = acc[e] + gb[e]; mx = fmaxf(mx, p[e]); }
        float s = 0.f;
#pragma unroll
        for (int e = 0; e < NE; e++) { p[e] = expf(p[e] - mx); s += p[e]; }
        float inv = 1.f / s;
#pragma unroll
        for (int e = 0; e < NE; e++) p[e] *= inv;

        // argmax (ties -> lowest index, matching lax.top_k)
        int i1 = 0;
#pragma unroll
        for (int e = 1; e < NE; e++) if (p[e] > p[i1]) i1 = e;
        int i2 = (i1 == 0) ? 1 : 0;
#pragma unroll
        for (int e = 0; e < NE; e++) if (e != i1 && p[e] > p[i2]) i2 = e;

        if (i1 == 0) {  // expert 0 contributes with its top-1 prob == p[0]
            int s0 = atomicAdd(&g_cnt[0], 1);
            g_idx[0][s0] = t; g_scale[0][s0] = p[0];
        }
        if (i2 == 1) {  // expert 1 contributes with its top-2 prob == p[1]
            int s1 = atomicAdd(&g_cnt[1], 1);
            g_idx[1][s1] = t; g_scale[1][s1] = p[1];
        }
    }
}

// GEMM1: gathered x rows [n x 1024] @ w1[e] [1024 x 2048] -> gelu(.+b1) into g_h.
// 64x64 tile, BK=16, 256 threads, 4x4 micro-tile.
__global__ __launch_bounds__(256) void ffn1_kernel(const float* __restrict__ x,
                                                   const float* __restrict__ w1,
                                                   const float* __restrict__ b1) {
    const int e  = blockIdx.z;
    const int n  = g_cnt[e];
    const int m0 = blockIdx.y * 64;
    if (m0 >= n) return;
    const int n0 = blockIdx.x * 64;
    const float* __restrict__ W = w1 + (size_t)e * DM * DF;

    __shared__ float As[16][64];
    __shared__ float Bs[16][64];

    const int tid  = threadIdx.x;
    const int arow = tid >> 2, aseg = tid & 3;
    const int brow = tid >> 4, bseg = tid & 15;
    const int ty   = tid >> 4, tx   = tid & 15;

    const float* aptr = 0;
    { int r = m0 + arow; if (r < n) aptr = x + (size_t)g_idx[e][r] * DM + aseg * 4; }

    float acc[4][4];
#pragma unroll
    for (int i = 0; i < 4; i++)
#pragma unroll
        for (int j = 0; j < 4; j++) acc[i][j] = 0.f;

    for (int k0 = 0; k0 < DM; k0 += 16) {
        float4 a = aptr ? *(const float4*)(aptr + k0) : make_float4(0.f, 0.f, 0.f, 0.f);
        As[aseg * 4 + 0][arow] = a.x; As[aseg * 4 + 1][arow] = a.y;
        As[aseg * 4 + 2][arow] = a.z; As[aseg * 4 + 3][arow] = a.w;
        *(float4*)&Bs[brow][bseg * 4] =
            *(const float4*)(W + (size_t)(k0 + brow) * DF + n0 + bseg * 4);
        __syncthreads();
#pragma unroll
        for (int k = 0; k < 16; k++) {
            float4 av = *(const float4*)&As[k][ty * 4];
            float4 bv = *(const float4*)&Bs[k][tx * 4];
            float ar[4] = {av.x, av.y, av.z, av.w};
            float br[4] = {bv.x, bv.y, bv.z, bv.w};
#pragma unroll
            for (int i = 0; i < 4; i++)
#pragma unroll
                for (int j = 0; j < 4; j++) acc[i][j] += ar[i] * br[j];
        }
        __syncthreads();
    }

    const float* bb = b1 + (size_t)e * DF + n0 + tx * 4;
#pragma unroll
    for (int i = 0; i < 4; i++) {
        int r = m0 + ty * 4 + i;
        if (r < n) {
            float* hp = &g_h[e][(size_t)r * DF + n0 + tx * 4];
#pragma unroll
            for (int j = 0; j < 4; j++) {
                float v = acc[i][j] + bb[j];
                hp[j] = 0.5f * v * (1.f + erff(v * 0.70710678118654752f));  // exact gelu
            }
        }
    }
}

// GEMM2: g_h [n x 2048] @ w2[e] [2048 x 1024] + b2, scaled scatter-add to out.
__global__ __launch_bounds__(256) void ffn2_kernel(const float* __restrict__ w2,
                                                   const float* __restrict__ b2,
                                                   float* __restrict__ out) {
    const int e  = blockIdx.z;
    const int n  = g_cnt[e];
    const int m0 = blockIdx.y * 64;
    if (m0 >= n) return;
    const int n0 = blockIdx.x * 64;
    const float* __restrict__ W = w2 + (size_t)e * DF * DM;
    const float* __restrict__ H = g_h[e];

    __shared__ float As[16][64];
    __shared__ float Bs[16][64];

    const int tid  = threadIdx.x;
    const int arow = tid >> 2, aseg = tid & 3;
    const int brow = tid >> 4, bseg = tid & 15;
    const int ty   = tid >> 4, tx   = tid & 15;

    const float* aptr = 0;
    { int r = m0 + arow; if (r < n) aptr = H + (size_t)r * DF + aseg * 4; }

    float acc[4][4];
#pragma unroll
    for (int i = 0; i < 4; i++)
#pragma unroll
        for (int j = 0; j < 4; j++) acc[i][j] = 0.f;

    for (int k0 = 0; k0 < DF; k0 += 16) {
        float4 a = aptr ? *(const float4*)(aptr + k0) : make_float4(0.f, 0.f, 0.f, 0.f);
        As[aseg * 4 + 0][arow] = a.x; As[aseg * 4 + 1][arow] = a.y;
        As[aseg * 4 + 2][arow] = a.z; As[aseg * 4 + 3][arow] = a.w;
        *(float4*)&Bs[brow][bseg * 4] =
            *(const float4*)(W + (size_t)(k0 + brow) * DM + n0 + bseg * 4);
        __syncthreads();
#pragma unroll
        for (int k = 0; k < 16; k++) {
            float4 av = *(const float4*)&As[k][ty * 4];
            float4 bv = *(const float4*)&Bs[k][tx * 4];
            float ar[4] = {av.x, av.y, av.z, av.w};
            float br[4] = {bv.x, bv.y, bv.z, bv.w};
#pragma unroll
            for (int i = 0; i < 4; i++)
#pragma unroll
                for (int j = 0; j < 4; j++) acc[i][j] += ar[i] * br[j];
        }
        __syncthreads();
    }

    const float* bb = b2 + (size_t)e * DM + n0 + tx * 4;
#pragma unroll
    for (int i = 0; i < 4; i++) {
        int r = m0 + ty * 4 + i;
        if (r < n) {
            int   tok = g_idx[e][r];
            float sc  = g_scale[e][r];
            float* op = out + (size_t)tok * DM + n0 + tx * 4;
#pragma unroll
            for (int j = 0; j < 4; j++)
                atomicAdd(op + j, sc * (acc[i][j] + bb[j]));  // <=2 commutative adds: deterministic
        }
    }
}

extern "C" void kernel_launch(void* const* d_in, const int* in_sizes, int n_in,
                              void* d_out, int out_size) {
    const float* x  = (const float*)d_in[0];
    const float* gw = (const float*)d_in[1];
    const float* gb = (const float*)d_in[2];
    const float* w1 = (const float*)d_in[3];
    const float* b1 = (const float*)d_in[4];
    const float* w2 = (const float*)d_in[5];
    const float* b2 = (const float*)d_in[6];
    float* out = (float*)d_out;

    // Zero output (inactive tokens stay 0) AND the lbl scalar (provably exactly 0).
    cudaMemsetAsync(out, 0, (size_t)out_size * sizeof(float), 0);

    reset_kernel<<<1, 32>>>();
    gate_kernel<<<TOKENS / 8, 256>>>(x, gw, gb);
    ffn1_kernel<<<dim3(DF / 64, TOKENS / 64, 2), 256>>>(x, w1, b1);
    ffn2_kernel<<<dim3(DM / 64, TOKENS / 64, 2), 256>>>(w2, b2, out);
}

// round 3
// speedup vs baseline: 1.9830x; 1.9830x over previous
#include <cuda_runtime.h>
#include <math.h>
#include <stdint.h>

#define TOKENS 8192
#define DM 1024
#define DF 2048
#define NE 8

// ---------------- scratch (device globals: allocation-free, graph-safe) -------------
__device__ int   g_cnt[2];
__device__ int   g_idx[2][TOKENS];
__device__ float g_scale[2][TOKENS];
__device__ float g_h[2][(size_t)TOKENS * DF];   // gelu activations, compacted rows

__global__ void reset_kernel() {
    if (threadIdx.x < 2) g_cnt[threadIdx.x] = 0;
}

// One warp per token: logits -> softmax -> top-2 -> compact active tokens (fp32, exact).
__global__ __launch_bounds__(256) void gate_kernel(const float* __restrict__ x,
                                                   const float* __restrict__ gw,
                                                   const float* __restrict__ gb) {
    __shared__ float sgw[DM * NE];
    for (int i = threadIdx.x; i < DM * NE; i += 256) sgw[i] = gw[i];
    __syncthreads();

    const int t    = (int)((blockIdx.x * 256u + threadIdx.x) >> 5);
    const int lane = threadIdx.x & 31;
    if (t >= TOKENS) return;

    const float* xr = x + (size_t)t * DM;
    float acc[NE];
#pragma unroll
    for (int e = 0; e < NE; e++) acc[e] = 0.f;
    for (int d = lane; d < DM; d += 32) {
        float xv = xr[d];
        const float4* wp = (const float4*)(sgw + d * NE);
        float4 w0 = wp[0], w1 = wp[1];
        acc[0] += xv * w0.x; acc[1] += xv * w0.y; acc[2] += xv * w0.z; acc[3] += xv * w0.w;
        acc[4] += xv * w1.x; acc[5] += xv * w1.y; acc[6] += xv * w1.z; acc[7] += xv * w1.w;
    }
#pragma unroll
    for (int e = 0; e < NE; e++)
#pragma unroll
        for (int o = 16; o > 0; o >>= 1) acc[e] += __shfl_xor_sync(0xffffffffu, acc[e], o);

    if (lane == 0) {
        float p[NE];
        float mx = -1e30f;
#pragma unroll
        for (int e = 0; e < NE; e++) { p[e] = acc[e] + gb[e]; mx = fmaxf(mx, p[e]); }
        float s = 0.f;
#pragma unroll
        for (int e = 0; e < NE; e++) { p[e] = expf(p[e] - mx); s += p[e]; }
        float inv = 1.f / s;
#pragma unroll
        for (int e = 0; e < NE; e++) p[e] *= inv;
        int i1 = 0;
#pragma unroll
        for (int e = 1; e < NE; e++) if (p[e] > p[i1]) i1 = e;
        int i2 = (i1 == 0) ? 1 : 0;
#pragma unroll
        for (int e = 0; e < NE; e++) if (e != i1 && p[e] > p[i2]) i2 = e;
        if (i1 == 0) { int s0 = atomicAdd(&g_cnt[0], 1); g_idx[0][s0] = t; g_scale[0][s0] = p[0]; }
        if (i2 == 1) { int s1 = atomicAdd(&g_cnt[1], 1); g_idx[1][s1] = t; g_scale[1][s1] = p[1]; }
    }
}

// ---------------- tf32 mma.sync GEMM ----------------
__device__ __forceinline__ float tf32r(float x) {
    float y;
    asm("cvt.rna.tf32.f32 %0, %1;" : "=f"(y) : "f"(x));
    return y;
}
__device__ __forceinline__ void mma_tf32(float* d, const uint32_t* a, const uint32_t* b) {
    asm volatile(
        "mma.sync.aligned.m16n8k8.row.col.f32.tf32.tf32.f32 "
        "{%0,%1,%2,%3}, {%4,%5,%6,%7}, {%8,%9}, {%0,%1,%2,%3};"
        : "+f"(d[0]), "+f"(d[1]), "+f"(d[2]), "+f"(d[3])
        : "r"(a[0]), "r"(a[1]), "r"(a[2]), "r"(a[3]), "r"(b[0]), "r"(b[1]));
}

#define AS_STRIDE 36
#define BS_STRIDE 136

// C-tile 128x128, BK=32. 8 warps: 2 (M) x 4 (N); warp tile 64x32.
template <int KTOT, bool IS_FFN1>
__global__ void __launch_bounds__(256, 2) ffn_mma_kernel(const float* __restrict__ x,
                                                         const float* __restrict__ W,
                                                         const float* __restrict__ bias,
                                                         float* __restrict__ outp) {
    const int e     = blockIdx.z;
    const int n_act = g_cnt[e];
    const int m0    = blockIdx.y * 128;
    if (m0 >= n_act) return;
    const int NOUT = IS_FFN1 ? DF : DM;
    const int n0   = blockIdx.x * 128;
    const float* __restrict__ Wq = W + (size_t)e * KTOT * NOUT;

    __shared__ float As[128][AS_STRIDE];
    __shared__ float Bs[32][BS_STRIDE];

    const int tid  = threadIdx.x;
    const int wid  = tid >> 5;
    const int lane = tid & 31;
    const int gid  = lane >> 2;   // group id 0..7
    const int tig  = lane & 3;    // thread-in-group 0..3
    const int wm0  = (wid >> 2) * 64;  // warp M origin (0/64)
    const int wn0  = (wid & 3) * 32;   // warp N origin (0/32/64/96)

    // A gather: thread covers row arow, 16 cols starting at aseg*16
    const int arow = tid >> 1, aseg = tid & 1;
    const float* aptr = nullptr;
    {
        int r = m0 + arow;
        if (r < n_act)
            aptr = IS_FFN1 ? (x + (size_t)g_idx[e][r] * DM) : (g_h[e] + (size_t)r * DF);
    }
    // B: thread covers k-row bk, 16 cols starting at bseg*16
    const int bk = tid >> 3, bseg = tid & 7;

    float c[4][4][4];
#pragma unroll
    for (int mi = 0; mi < 4; mi++)
#pragma unroll
        for (int ni = 0; ni < 4; ni++)
#pragma unroll
            for (int q = 0; q < 4; q++) c[mi][ni][q] = 0.f;

    for (int k0 = 0; k0 < KTOT; k0 += 32) {
        // global loads first (overlap with previous compute before syncs)
        float4 av[4], bv[4];
#pragma unroll
        for (int i = 0; i < 4; i++) {
            av[i] = aptr ? *(const float4*)(aptr + k0 + aseg * 16 + i * 4)
                         : make_float4(0.f, 0.f, 0.f, 0.f);
            bv[i] = *(const float4*)(Wq + (size_t)(k0 + bk) * NOUT + n0 + bseg * 16 + i * 4);
        }
        __syncthreads();
#pragma unroll
        for (int i = 0; i < 4; i++) {
            float4 a = av[i];
            a.x = tf32r(a.x); a.y = tf32r(a.y); a.z = tf32r(a.z); a.w = tf32r(a.w);
            *(float4*)&As[arow][aseg * 16 + i * 4] = a;
            float4 b = bv[i];
            b.x = tf32r(b.x); b.y = tf32r(b.y); b.z = tf32r(b.z); b.w = tf32r(b.w);
            *(float4*)&Bs[bk][bseg * 16 + i * 4] = b;
        }
        __syncthreads();

#pragma unroll
        for (int ks = 0; ks < 4; ks++) {
            const int kk = ks * 8;
            uint32_t a[4][4], b[4][2];
#pragma unroll
            for (int mi = 0; mi < 4; mi++) {
                const int r = wm0 + mi * 16 + gid;
                a[mi][0] = __float_as_uint(As[r][kk + tig]);
                a[mi][1] = __float_as_uint(As[r + 8][kk + tig]);
                a[mi][2] = __float_as_uint(As[r][kk + tig + 4]);
                a[mi][3] = __float_as_uint(As[r + 8][kk + tig + 4]);
            }
#pragma unroll
            for (int ni = 0; ni < 4; ni++) {
                const int nn = wn0 + ni * 8 + gid;
                b[ni][0] = __float_as_uint(Bs[kk + tig][nn]);
                b[ni][1] = __float_as_uint(Bs[kk + tig + 4][nn]);
            }
#pragma unroll
            for (int mi = 0; mi < 4; mi++)
#pragma unroll
                for (int ni = 0; ni < 4; ni++) mma_tf32(c[mi][ni], a[mi], b[ni]);
        }
    }

    // ---------------- epilogue ----------------
    const float* bb = bias + (size_t)e * NOUT + n0;
    if (IS_FFN1) {
#pragma unroll
        for (int mi = 0; mi < 4; mi++) {
#pragma unroll
            for (int half = 0; half < 2; half++) {
                const int r = m0 + wm0 + mi * 16 + gid + half * 8;
                if (r < n_act) {
                    float* hrow = g_h[e] + (size_t)r * DF + n0;
#pragma unroll
                    for (int ni = 0; ni < 4; ni++) {
                        const int nn = wn0 + ni * 8 + 2 * tig;
                        float v0 = c[mi][ni][2 * half + 0] + bb[nn];
                        float v1 = c[mi][ni][2 * half + 1] + bb[nn + 1];
                        float2 o;
                        o.x = 0.5f * v0 * (1.f + erff(v0 * 0.70710678118654752f));
                        o.y = 0.5f * v1 * (1.f + erff(v1 * 0.70710678118654752f));
                        *(float2*)(hrow + nn) = o;
                    }
                }
            }
        }
    } else {
#pragma unroll
        for (int mi = 0; mi < 4; mi++) {
#pragma unroll
            for (int half = 0; half < 2; half++) {
                const int r = m0 + wm0 + mi * 16 + gid + half * 8;
                if (r < n_act) {
                    const int   tok = g_idx[e][r];
                    const float sc  = g_scale[e][r];
                    float* orow = outp + (size_t)tok * DM + n0;
#pragma unroll
                    for (int ni = 0; ni < 4; ni++) {
                        const int nn = wn0 + ni * 8 + 2 * tig;
                        atomicAdd(orow + nn,     sc * (c[mi][ni][2 * half + 0] + bb[nn]));
                        atomicAdd(orow + nn + 1, sc * (c[mi][ni][2 * half + 1] + bb[nn + 1]));
                    }
                }
            }
        }
    }
}

extern "C" void kernel_launch(void* const* d_in, const int* in_sizes, int n_in,
                              void* d_out, int out_size) {
    const float* x  = (const float*)d_in[0];
    const float* gw = (const float*)d_in[1];
    const float* gb = (const float*)d_in[2];
    const float* w1 = (const float*)d_in[3];
    const float* b1 = (const float*)d_in[4];
    const float* w2 = (const float*)d_in[5];
    const float* b2 = (const float*)d_in[6];
    float* out = (float*)d_out;

    cudaMemsetAsync(out, 0, (size_t)out_size * sizeof(float), 0);
    reset_kernel<<<1, 32>>>();
    gate_kernel<<<TOKENS / 8, 256>>>(x, gw, gb);
    ffn_mma_kernel<DM, true><<<dim3(DF / 128, TOKENS / 128, 2), 256>>>(x, w1, b1, nullptr);
    ffn_mma_kernel<DF, false><<<dim3(DM / 128, TOKENS / 128, 2), 256>>>(x, w2, b2, out);
}

// round 4
// speedup vs baseline: 2.7271x; 1.3753x over previous
#include <cuda_runtime.h>
#include <math.h>
#include <stdint.h>

#define TOKENS 8192
#define DM 1024
#define DF 2048
#define NE 8

// ---------------- scratch (device globals: allocation-free, graph-safe) -------------
__device__ int   g_cnt[2];
__device__ int   g_idx[2][TOKENS];
__device__ float g_scale[2][TOKENS];
__device__ float g_h[2][(size_t)TOKENS * DF];

__global__ void reset_kernel() {
    if (threadIdx.x < 2) g_cnt[threadIdx.x] = 0;
}

// One warp per token: logits -> softmax -> top-2 -> compact active tokens (fp32, exact).
__global__ __launch_bounds__(256) void gate_kernel(const float* __restrict__ x,
                                                   const float* __restrict__ gw,
                                                   const float* __restrict__ gb) {
    __shared__ float sgw[DM * NE];
    for (int i = threadIdx.x; i < DM * NE; i += 256) sgw[i] = gw[i];
    __syncthreads();

    const int t    = (int)((blockIdx.x * 256u + threadIdx.x) >> 5);
    const int lane = threadIdx.x & 31;
    if (t >= TOKENS) return;

    const float* xr = x + (size_t)t * DM;
    float acc[NE];
#pragma unroll
    for (int e = 0; e < NE; e++) acc[e] = 0.f;
    for (int d = lane; d < DM; d += 32) {
        float xv = xr[d];
        const float4* wp = (const float4*)(sgw + d * NE);
        float4 w0 = wp[0], w1 = wp[1];
        acc[0] += xv * w0.x; acc[1] += xv * w0.y; acc[2] += xv * w0.z; acc[3] += xv * w0.w;
        acc[4] += xv * w1.x; acc[5] += xv * w1.y; acc[6] += xv * w1.z; acc[7] += xv * w1.w;
    }
#pragma unroll
    for (int e = 0; e < NE; e++)
#pragma unroll
        for (int o = 16; o > 0; o >>= 1) acc[e] += __shfl_xor_sync(0xffffffffu, acc[e], o);

    if (lane == 0) {
        float p[NE];
        float mx = -1e30f;
#pragma unroll
        for (int e = 0; e < NE; e++) { p[e] = acc[e] + gb[e]; mx = fmaxf(mx, p[e]); }
        float s = 0.f;
#pragma unroll
        for (int e = 0; e < NE; e++) { p[e] = expf(p[e] - mx); s += p[e]; }
        float inv = 1.f / s;
#pragma unroll
        for (int e = 0; e < NE; e++) p[e] *= inv;
        int i1 = 0;
#pragma unroll
        for (int e = 1; e < NE; e++) if (p[e] > p[i1]) i1 = e;
        int i2 = (i1 == 0) ? 1 : 0;
#pragma unroll
        for (int e = 0; e < NE; e++) if (e != i1 && p[e] > p[i2]) i2 = e;
        if (i1 == 0) { int s0 = atomicAdd(&g_cnt[0], 1); g_idx[0][s0] = t; g_scale[0][s0] = p[0]; }
        if (i2 == 1) { int s1 = atomicAdd(&g_cnt[1], 1); g_idx[1][s1] = t; g_scale[1][s1] = p[1]; }
    }
}

// ---------------- tf32 mma.sync GEMM with cp.async pipeline ----------------
__device__ __forceinline__ float tf32r(float x) {
    float y;
    asm("cvt.rna.tf32.f32 %0, %1;" : "=f"(y) : "f"(x));
    return y;
}
__device__ __forceinline__ void mma_tf32(float* d, const uint32_t* a, const uint32_t* b) {
    asm volatile(
        "mma.sync.aligned.m16n8k8.row.col.f32.tf32.tf32.f32 "
        "{%0,%1,%2,%3}, {%4,%5,%6,%7}, {%8,%9}, {%0,%1,%2,%3};"
        : "+f"(d[0]), "+f"(d[1]), "+f"(d[2]), "+f"(d[3])
        : "r"(a[0]), "r"(a[1]), "r"(a[2]), "r"(a[3]), "r"(b[0]), "r"(b[1]));
}
__device__ __forceinline__ uint32_t smem_u32(const void* p) {
    uint32_t a;
    asm("{ .reg .u64 t; cvta.to.shared.u64 t, %1; cvt.u32.u64 %0, t; }" : "=r"(a) : "l"(p));
    return a;
}
#define CP_ASYNC16(dst, src, srcsz) \
    asm volatile("cp.async.cg.shared.global [%0], [%1], 16, %2;" \
                 :: "r"(dst), "l"(src), "r"(srcsz))
#define CP_COMMIT() asm volatile("cp.async.commit_group;" ::: "memory")
#define CP_WAIT1()  asm volatile("cp.async.wait_group 1;" ::: "memory")

#define AS_STRIDE 36
#define BS_STRIDE 136
#define STAGES 3
#define AS_FLOATS (128 * AS_STRIDE)
#define STAGE_FLOATS (AS_FLOATS + 32 * BS_STRIDE)
#define STAGE_BYTES (STAGE_FLOATS * 4)
#define SMEM_TOTAL (STAGES * STAGE_BYTES)

// C-tile 128x128, BK=32. 8 warps: 2 (M) x 4 (N); warp tile 64x32.
// SPLITK: ffn2 splits K across blockIdx.z parity (output is atomic scatter-add).
template <int KSLICE, bool IS_FFN1, int SPLITK>
__global__ void __launch_bounds__(256, 1) ffn_mma_kernel(const float* __restrict__ x,
                                                         const float* __restrict__ W,
                                                         const float* __restrict__ bias,
                                                         float* __restrict__ outp) {
    const int e     = blockIdx.z / SPLITK;
    const int split = blockIdx.z % SPLITK;
    const int n_act = g_cnt[e];
    const int m0    = blockIdx.y * 128;
    if (m0 >= n_act) return;
    const int NOUT  = IS_FFN1 ? DF : DM;
    const int KTOT  = IS_FFN1 ? DM : DF;
    const int n0    = blockIdx.x * 128;
    const int kbase = split * KSLICE;
    const float* __restrict__ Wq = W + (size_t)e * KTOT * NOUT;

    extern __shared__ float dynsmem[];

    const int tid  = threadIdx.x;
    const int wid  = tid >> 5;
    const int lane = tid & 31;
    const int gid  = lane >> 2;
    const int tig  = lane & 3;
    const int wm0  = (wid >> 2) * 64;
    const int wn0  = (wid & 3) * 32;

    // A gather: thread covers row arow, 16 cols starting at aseg*16
    const int arow = tid >> 1, aseg = tid & 1;
    const float* aptr;
    uint32_t a_sz;
    {
        int r = m0 + arow;
        bool v = r < n_act;
        int ridx = v ? (IS_FFN1 ? g_idx[e][r] : r) : 0;
        aptr = (IS_FFN1 ? (x + (size_t)ridx * DM) : (g_h[e] + (size_t)ridx * DF))
               + kbase + aseg * 16;
        a_sz = v ? 16u : 0u;   // zero-fill inactive rows
    }
    // B: thread covers k-row bk, 16 cols starting at bseg*16
    const int bk = tid >> 3, bseg = tid & 7;
    const float* bptr = Wq + (size_t)(kbase + bk) * NOUT + n0 + bseg * 16;

    const uint32_t as_dst = smem_u32(dynsmem) + (uint32_t)((arow * AS_STRIDE + aseg * 16) * 4);
    const uint32_t bs_dst = smem_u32(dynsmem) +
                            (uint32_t)((AS_FLOATS + bk * BS_STRIDE + bseg * 16) * 4);

    const int NCHUNK = KSLICE / 32;

    auto issue = [&](int chunk) {
        if (chunk < NCHUNK) {
            const uint32_t sb = (uint32_t)((chunk % STAGES) * STAGE_BYTES);
            const float* ap = aptr + chunk * 32;
            const float* bp = bptr + (size_t)chunk * 32 * NOUT;
#pragma unroll
            for (int i = 0; i < 4; i++)
                CP_ASYNC16(as_dst + sb + i * 16, ap + i * 4, a_sz);
#pragma unroll
            for (int i = 0; i < 4; i++)
                CP_ASYNC16(bs_dst + sb + i * 16, bp + i * 4, 16u);
        }
        CP_COMMIT();   // uniform groups: wait_group(1) always pins chunk i
    };

    float c[4][4][4];
#pragma unroll
    for (int mi = 0; mi < 4; mi++)
#pragma unroll
        for (int ni = 0; ni < 4; ni++)
#pragma unroll
            for (int q = 0; q < 4; q++) c[mi][ni][q] = 0.f;

    issue(0);
    issue(1);

    for (int i = 0; i < NCHUNK; i++) {
        CP_WAIT1();
        __syncthreads();
        const float* As = dynsmem + (i % STAGES) * STAGE_FLOATS;
        const float* Bs = As + AS_FLOATS;

#pragma unroll
        for (int ks = 0; ks < 4; ks++) {
            const int kk = ks * 8;
            uint32_t a[4][4], b[4][2];
#pragma unroll
            for (int mi = 0; mi < 4; mi++) {
                const int r = wm0 + mi * 16 + gid;
                a[mi][0] = __float_as_uint(tf32r(As[r * AS_STRIDE + kk + tig]));
                a[mi][1] = __float_as_uint(tf32r(As[(r + 8) * AS_STRIDE + kk + tig]));
                a[mi][2] = __float_as_uint(tf32r(As[r * AS_STRIDE + kk + tig + 4]));
                a[mi][3] = __float_as_uint(tf32r(As[(r + 8) * AS_STRIDE + kk + tig + 4]));
            }
#pragma unroll
            for (int ni = 0; ni < 4; ni++) {
                const int nn = wn0 + ni * 8 + gid;
                b[ni][0] = __float_as_uint(tf32r(Bs[(kk + tig) * BS_STRIDE + nn]));
                b[ni][1] = __float_as_uint(tf32r(Bs[(kk + tig + 4) * BS_STRIDE + nn]));
            }
#pragma unroll
            for (int mi = 0; mi < 4; mi++)
#pragma unroll
                for (int ni = 0; ni < 4; ni++) mma_tf32(c[mi][ni], a[mi], b[ni]);
        }
        __syncthreads();
        issue(i + 2);
    }

    // ---------------- epilogue ----------------
    const float* bb = bias + (size_t)e * NOUT + n0;
    if (IS_FFN1) {
#pragma unroll
        for (int mi = 0; mi < 4; mi++) {
#pragma unroll
            for (int half = 0; half < 2; half++) {
                const int r = m0 + wm0 + mi * 16 + gid + half * 8;
                if (r < n_act) {
                    float* hrow = g_h[e] + (size_t)r * DF + n0;
#pragma unroll
                    for (int ni = 0; ni < 4; ni++) {
                        const int nn = wn0 + ni * 8 + 2 * tig;
                        float v0 = c[mi][ni][2 * half + 0] + bb[nn];
                        float v1 = c[mi][ni][2 * half + 1] + bb[nn + 1];
                        float2 o;
                        o.x = 0.5f * v0 * (1.f + erff(v0 * 0.70710678118654752f));
                        o.y = 0.5f * v1 * (1.f + erff(v1 * 0.70710678118654752f));
                        *(float2*)(hrow + nn) = o;
                    }
                }
            }
        }
    } else {
#pragma unroll
        for (int mi = 0; mi < 4; mi++) {
#pragma unroll
            for (int half = 0; half < 2; half++) {
                const int r = m0 + wm0 + mi * 16 + gid + half * 8;
                if (r < n_act) {
                    const int   tok = g_idx[e][r];
                    const float sc  = g_scale[e][r];
                    float* orow = outp + (size_t)tok * DM + n0;
#pragma unroll
                    for (int ni = 0; ni < 4; ni++) {
                        const int nn = wn0 + ni * 8 + 2 * tig;
                        float bb0 = (split == 0) ? bb[nn]     : 0.f;  // bias added once
                        float bb1 = (split == 0) ? bb[nn + 1] : 0.f;
                        atomicAdd(orow + nn,     sc * (c[mi][ni][2 * half + 0] + bb0));
                        atomicAdd(orow + nn + 1, sc * (c[mi][ni][2 * half + 1] + bb1));
                    }
                }
            }
        }
    }
}

extern "C" void kernel_launch(void* const* d_in, const int* in_sizes, int n_in,
                              void* d_out, int out_size) {
    const float* x  = (const float*)d_in[0];
    const float* gw = (const float*)d_in[1];
    const float* gb = (const float*)d_in[2];
    const float* w1 = (const float*)d_in[3];
    const float* b1 = (const float*)d_in[4];
    const float* w2 = (const float*)d_in[5];
    const float* b2 = (const float*)d_in[6];
    float* out = (float*)d_out;

    cudaFuncSetAttribute(ffn_mma_kernel<DM, true, 1>,
                         cudaFuncAttributeMaxDynamicSharedMemorySize, SMEM_TOTAL);
    cudaFuncSetAttribute(ffn_mma_kernel<DF / 2, false, 2>,
                         cudaFuncAttributeMaxDynamicSharedMemorySize, SMEM_TOTAL);

    cudaMemsetAsync(out, 0, (size_t)out_size * sizeof(float), 0);
    reset_kernel<<<1, 32>>>();
    gate_kernel<<<TOKENS / 8, 256>>>(x, gw, gb);
    // ffn1: full K=1024 per CTA
    ffn_mma_kernel<DM, true, 1>
        <<<dim3(DF / 128, TOKENS / 128, 2), 256, SMEM_TOTAL>>>(x, w1, b1, nullptr);
    // ffn2: split-K=2 (K slice 1024 each), z = expert*2 + split
    ffn_mma_kernel<DF / 2, false, 2>
        <<<dim3(DM / 128, TOKENS / 128, 4), 256, SMEM_TOTAL>>>(x, w2, b2, out);
}